// round 1
// baseline (speedup 1.0000x reference)
#include <cuda_runtime.h>
#include <math.h>

#define BB   8
#define NN   4096
#define TILE 2048
#define TPB  256
#define NBLK_X (NN / TPB)            // 16 query-chunks per (batch,dir)
#define NPART (2 * BB * NBLK_X)      // 256 partial sums

// Scratch (no allocation allowed): transformed points as float4 (x,y,z, 0.5*|p|^2)
__device__ float4 g_pts[2][BB][NN];      // [0]=pred, [1]=gt
__device__ float  g_relrot[2][BB][9];
__device__ float  g_reltrans[2][BB][3];
__device__ float  g_partials[NPART];

// ---------------------------------------------------------------------------
// Kernel 1: relative transforms (tiny) + loss_trans
// ---------------------------------------------------------------------------
__global__ void k_setup(const float* __restrict__ pred_rot,
                        const float* __restrict__ pred_trans,
                        const float* __restrict__ ctx_hyp_rot,
                        const float* __restrict__ ctx_hyp_trans,
                        const float* __restrict__ gt_rot,
                        const float* __restrict__ gt_trans,
                        const float* __restrict__ ctx_gt_rot,
                        const float* __restrict__ ctx_gt_trans,
                        float* __restrict__ out)
{
    int tid = threadIdx.x;
    if (tid < 2 * BB) {
        int which = tid / BB;   // 0 = pred, 1 = gt
        int b     = tid % BB;
        const float* Ra = (which == 0 ? pred_rot   : gt_rot)     + b * 9;
        const float* ta = (which == 0 ? pred_trans : gt_trans)   + b * 3;
        const float* Rb = (which == 0 ? ctx_hyp_rot : ctx_gt_rot) + b * 9;
        const float* tb = (which == 0 ? ctx_hyp_trans : ctx_gt_trans) + b * 3;

        float R[9];
        #pragma unroll
        for (int i = 0; i < 3; i++)
            #pragma unroll
            for (int k = 0; k < 3; k++) {
                float s = 0.f;
                #pragma unroll
                for (int j = 0; j < 3; j++) s += Ra[i*3 + j] * Rb[k*3 + j];
                R[i*3 + k] = s;
                g_relrot[which][b][i*3 + k] = s;
            }
        #pragma unroll
        for (int i = 0; i < 3; i++) {
            float s = ta[i];
            #pragma unroll
            for (int j = 0; j < 3; j++) s -= R[i*3 + j] * tb[j];
            g_reltrans[which][b][i] = s;
        }
    }
    __syncthreads();
    if (tid == 0) {
        float s = 0.f;
        for (int b = 0; b < BB; b++)
            for (int i = 0; i < 3; i++)
                s += fabsf(g_reltrans[0][b][i] - g_reltrans[1][b][i]);
        out[1] = s * (1.0f / (BB * 3));
    }
}

// ---------------------------------------------------------------------------
// Kernel 2: transform model points through both relative transforms,
//           store float4 (x, y, z, half-squared-norm)
// ---------------------------------------------------------------------------
__global__ void k_transform(const float* __restrict__ mp)
{
    int idx = blockIdx.x * blockDim.x + threadIdx.x;   // < BB*NN
    int b = idx >> 12;
    int n = idx & (NN - 1);
    float px = mp[idx * 3 + 0];
    float py = mp[idx * 3 + 1];
    float pz = mp[idx * 3 + 2];
    #pragma unroll
    for (int w = 0; w < 2; w++) {
        const float* R = g_relrot[w][b];
        const float* t = g_reltrans[w][b];
        float x = fmaf(R[0], px, fmaf(R[1], py, fmaf(R[2], pz, t[0])));
        float y = fmaf(R[3], px, fmaf(R[4], py, fmaf(R[5], pz, t[1])));
        float z = fmaf(R[6], px, fmaf(R[7], py, fmaf(R[8], pz, t[2])));
        float h = 0.5f * fmaf(x, x, fmaf(y, y, z * z));
        g_pts[w][b][n] = make_float4(x, y, z, h);
    }
}

// ---------------------------------------------------------------------------
// Block reduction (sum), deterministic
// ---------------------------------------------------------------------------
__device__ __forceinline__ float block_reduce_sum(float v)
{
    __shared__ float warp_sums[TPB / 32];
    #pragma unroll
    for (int o = 16; o > 0; o >>= 1)
        v += __shfl_down_sync(0xffffffffu, v, o);
    if ((threadIdx.x & 31) == 0) warp_sums[threadIdx.x >> 5] = v;
    __syncthreads();
    if (threadIdx.x < 32) {
        v = (threadIdx.x < TPB / 32) ? warp_sums[threadIdx.x] : 0.f;
        #pragma unroll
        for (int o = 4; o > 0; o >>= 1)
            v += __shfl_down_sync(0xffffffffu, v, o);
    }
    return v;  // valid in thread 0
}

// ---------------------------------------------------------------------------
// Kernel 3: one-directional chamfer min per query point.
//   dir=0: queries=pred pts, targets=gt pts  (row min)
//   dir=1: queries=gt pts,  targets=pred pts (col min)
// min over targets of (h_t - q·t); dist = sqrt(max(2*(min + h_q), 0)).
// sqrt deferred to the minimum only (monotone).
// ---------------------------------------------------------------------------
__global__ void __launch_bounds__(TPB) k_chamfer()
{
    __shared__ float4 sh[TILE];

    const int dir = blockIdx.z;
    const int b   = blockIdx.y;
    const int n   = blockIdx.x * TPB + threadIdx.x;

    const float4* __restrict__ ts = &g_pts[1 - dir][b][0];
    float4 q = g_pts[dir][b][n];
    const float nax = -q.x, nay = -q.y, naz = -q.z;

    float m0 = INFINITY, m1 = INFINITY, m2 = INFINITY, m3 = INFINITY;

    for (int base = 0; base < NN; base += TILE) {
        __syncthreads();
        #pragma unroll
        for (int j = threadIdx.x; j < TILE; j += TPB)
            sh[j] = ts[base + j];
        __syncthreads();

        #pragma unroll 4
        for (int j = 0; j < TILE; j += 4) {
            float4 p0 = sh[j + 0];
            float4 p1 = sh[j + 1];
            float4 p2 = sh[j + 2];
            float4 p3 = sh[j + 3];
            float v0 = fmaf(nax, p0.x, fmaf(nay, p0.y, fmaf(naz, p0.z, p0.w)));
            float v1 = fmaf(nax, p1.x, fmaf(nay, p1.y, fmaf(naz, p1.z, p1.w)));
            float v2 = fmaf(nax, p2.x, fmaf(nay, p2.y, fmaf(naz, p2.z, p2.w)));
            float v3 = fmaf(nax, p3.x, fmaf(nay, p3.y, fmaf(naz, p3.z, p3.w)));
            m0 = fminf(m0, v0);
            m1 = fminf(m1, v1);
            m2 = fminf(m2, v2);
            m3 = fminf(m3, v3);
        }
    }

    float m = fminf(fminf(m0, m1), fminf(m2, m3));
    float d = sqrtf(fmaxf(2.0f * (m + q.w), 0.0f));

    float s = block_reduce_sum(d);
    if (threadIdx.x == 0)
        g_partials[(blockIdx.z * BB + blockIdx.y) * NBLK_X + blockIdx.x] = s;
}

// ---------------------------------------------------------------------------
// Kernel 4: final reduce of 256 partials -> loss_geo
// loss_geo = (1/(B*N)) * sum over both directions of all per-point min dists
// ---------------------------------------------------------------------------
__global__ void k_final(float* __restrict__ out)
{
    float v = g_partials[threadIdx.x];   // exactly NPART=256 threads
    float s = block_reduce_sum(v);
    if (threadIdx.x == 0)
        out[0] = s * (1.0f / (BB * NN));
}

// ---------------------------------------------------------------------------
extern "C" void kernel_launch(void* const* d_in, const int* in_sizes, int n_in,
                              void* d_out, int out_size)
{
    const float* pred_rot      = (const float*)d_in[0];
    const float* pred_trans    = (const float*)d_in[1];
    const float* ctx_hyp_rot   = (const float*)d_in[2];
    const float* ctx_hyp_trans = (const float*)d_in[3];
    const float* gt_rot        = (const float*)d_in[4];
    const float* gt_trans      = (const float*)d_in[5];
    const float* ctx_gt_rot    = (const float*)d_in[6];
    const float* ctx_gt_trans  = (const float*)d_in[7];
    const float* model_points  = (const float*)d_in[8];
    float* out = (float*)d_out;

    k_setup<<<1, 32>>>(pred_rot, pred_trans, ctx_hyp_rot, ctx_hyp_trans,
                       gt_rot, gt_trans, ctx_gt_rot, ctx_gt_trans, out);
    k_transform<<<(BB * NN) / TPB, TPB>>>(model_points);
    k_chamfer<<<dim3(NBLK_X, BB, 2), TPB>>>();
    k_final<<<1, NPART>>>(out);
}

// round 2
// speedup vs baseline: 1.4164x; 1.4164x over previous
#include <cuda_runtime.h>
#include <math.h>

#define BB   8
#define NN   4096
#define TPB  256
#define QPT  2                    // queries per thread
#define QPB  (TPB * QPT)          // 512 queries per block
#define NCHUNK (NN / QPB)         // 8
#define NBLK (2 * BB * NCHUNK)    // 128 chamfer blocks
#define PSTEPS (NN / 2)           // 2048 packed target-pairs
#define TILE_P 1024               // packed pairs per smem tile (2048 targets -> 2 tiles)

typedef unsigned long long ull;

// Scratch (__device__ globals; allocation is forbidden)
__device__ float4 g_xy[2][BB][PSTEPS];   // (x_{2j}, x_{2j+1}, y_{2j}, y_{2j+1})
__device__ float4 g_zh[2][BB][PSTEPS];   // (z_{2j}, z_{2j+1}, h_{2j}, h_{2j+1}) ; h = 0.5*|p|^2
__device__ float4 g_q [2][BB][NN];       // AoS queries (x,y,z,h)
__device__ float  g_partials[NBLK];
__device__ unsigned int g_count = 0;

// ---- packed f32x2 helpers (sm_103a) --------------------------------------
__device__ __forceinline__ ull fma2(ull a, ull b, ull c) {
    ull d;
    asm("fma.rn.f32x2 %0, %1, %2, %3;" : "=l"(d) : "l"(a), "l"(b), "l"(c));
    return d;
}
__device__ __forceinline__ ull pack2(float lo, float hi) {
    ull r;
    asm("mov.b64 %0, {%1, %2};" : "=l"(r) : "f"(lo), "f"(hi));
    return r;
}
__device__ __forceinline__ void unpack2(ull v, float& lo, float& hi) {
    asm("mov.b64 {%0, %1}, %2;" : "=f"(lo), "=f"(hi) : "l"(v));
}

// ---------------------------------------------------------------------------
// Kernel 1: fused setup (relative transforms, recomputed per block in smem)
//           + point transform into packed SoA layout + loss_trans.
// grid: BB*NN/2 threads, each handles 2 consecutive points.
// ---------------------------------------------------------------------------
__global__ void __launch_bounds__(TPB) k_prep(
    const float* __restrict__ pred_rot,   const float* __restrict__ pred_trans,
    const float* __restrict__ ctx_hyp_rot,const float* __restrict__ ctx_hyp_trans,
    const float* __restrict__ gt_rot,     const float* __restrict__ gt_trans,
    const float* __restrict__ ctx_gt_rot, const float* __restrict__ ctx_gt_trans,
    const float* __restrict__ mp,         float* __restrict__ out)
{
    __shared__ float sR[2][BB][9];
    __shared__ float sT[2][BB][3];

    const int tid = threadIdx.x;
    if (tid < 2 * BB) {
        const int w = tid / BB;                 // 0 = pred, 1 = gt
        const int b = tid % BB;
        const float* Ra = (w == 0 ? pred_rot      : gt_rot)      + b * 9;
        const float* ta = (w == 0 ? pred_trans    : gt_trans)    + b * 3;
        const float* Rb = (w == 0 ? ctx_hyp_rot   : ctx_gt_rot)  + b * 9;
        const float* tb = (w == 0 ? ctx_hyp_trans : ctx_gt_trans)+ b * 3;
        #pragma unroll
        for (int i = 0; i < 3; i++) {
            #pragma unroll
            for (int k = 0; k < 3; k++) {
                float s = 0.f;
                #pragma unroll
                for (int j = 0; j < 3; j++) s += Ra[i*3+j] * Rb[k*3+j];
                sR[w][b][i*3+k] = s;
            }
        }
        #pragma unroll
        for (int i = 0; i < 3; i++) {
            float s = ta[i];
            #pragma unroll
            for (int j = 0; j < 3; j++) s -= sR[w][b][i*3+j] * tb[j];
            sT[w][b][i] = s;
        }
    }
    __syncthreads();

    if (blockIdx.x == 0 && tid == 0) {
        float s = 0.f;
        for (int b = 0; b < BB; b++)
            for (int i = 0; i < 3; i++)
                s += fabsf(sT[0][b][i] - sT[1][b][i]);
        out[1] = s * (1.0f / (BB * 3));
    }

    const int idx = blockIdx.x * TPB + tid;         // < BB * NN/2
    const int b = idx / PSTEPS;
    const int i = idx % PSTEPS;                     // packed pair index
    const float* p = mp + (b * NN + 2 * i) * 3;
    const float p0x = p[0], p0y = p[1], p0z = p[2];
    const float p1x = p[3], p1y = p[4], p1z = p[5];

    #pragma unroll
    for (int w = 0; w < 2; w++) {
        const float* R = sR[w][b];
        const float* t = sT[w][b];
        float x0 = fmaf(R[0], p0x, fmaf(R[1], p0y, fmaf(R[2], p0z, t[0])));
        float y0 = fmaf(R[3], p0x, fmaf(R[4], p0y, fmaf(R[5], p0z, t[1])));
        float z0 = fmaf(R[6], p0x, fmaf(R[7], p0y, fmaf(R[8], p0z, t[2])));
        float h0 = 0.5f * fmaf(x0, x0, fmaf(y0, y0, z0 * z0));
        float x1 = fmaf(R[0], p1x, fmaf(R[1], p1y, fmaf(R[2], p1z, t[0])));
        float y1 = fmaf(R[3], p1x, fmaf(R[4], p1y, fmaf(R[5], p1z, t[1])));
        float z1 = fmaf(R[6], p1x, fmaf(R[7], p1y, fmaf(R[8], p1z, t[2])));
        float h1 = 0.5f * fmaf(x1, x1, fmaf(y1, y1, z1 * z1));
        g_xy[w][b][i] = make_float4(x0, x1, y0, y1);
        g_zh[w][b][i] = make_float4(z0, z1, h0, h1);
        g_q [w][b][2*i  ] = make_float4(x0, y0, z0, h0);
        g_q [w][b][2*i+1] = make_float4(x1, y1, z1, h1);
    }
}

// ---------------------------------------------------------------------------
// Deterministic block sum reduction (result valid in thread 0)
// ---------------------------------------------------------------------------
__device__ __forceinline__ float block_reduce_sum(float v)
{
    __shared__ float ws[TPB / 32];
    #pragma unroll
    for (int o = 16; o > 0; o >>= 1) v += __shfl_down_sync(0xffffffffu, v, o);
    if ((threadIdx.x & 31) == 0) ws[threadIdx.x >> 5] = v;
    __syncthreads();
    if (threadIdx.x < 32) {
        v = (threadIdx.x < TPB / 32) ? ws[threadIdx.x] : 0.f;
        #pragma unroll
        for (int o = 4; o > 0; o >>= 1) v += __shfl_down_sync(0xffffffffu, v, o);
    }
    return v;
}

// ---------------------------------------------------------------------------
// Kernel 2: chamfer. Each thread: 2 queries, packed-f32x2 sweep over all
// targets (2 targets per fma2). Per (b,dir): min over targets of (h_t - q.t);
// dist = sqrt(max(2*(min + h_q), 0)) -- sqrt deferred past the min.
// Last finished block reduces the 128 partials (deterministic fixed order).
// ---------------------------------------------------------------------------
__global__ void __launch_bounds__(TPB) k_chamfer(float* __restrict__ out)
{
    __shared__ float4 s_xy[TILE_P];
    __shared__ float4 s_zh[TILE_P];

    const int dir = blockIdx.z;
    const int b   = blockIdx.y;
    const int tid = threadIdx.x;
    const int n0  = blockIdx.x * QPB + tid;
    const int n1  = n0 + TPB;

    const float4 q0 = g_q[dir][b][n0];
    const float4 q1 = g_q[dir][b][n1];
    const ull nx0 = pack2(-q0.x, -q0.x);
    const ull ny0 = pack2(-q0.y, -q0.y);
    const ull nz0 = pack2(-q0.z, -q0.z);
    const ull nx1 = pack2(-q1.x, -q1.x);
    const ull ny1 = pack2(-q1.y, -q1.y);
    const ull nz1 = pack2(-q1.z, -q1.z);

    float m0a = INFINITY, m0b = INFINITY, m1a = INFINITY, m1b = INFINITY;

    const float4* __restrict__ gxy = &g_xy[1 - dir][b][0];
    const float4* __restrict__ gzh = &g_zh[1 - dir][b][0];

    #pragma unroll
    for (int t = 0; t < PSTEPS / TILE_P; t++) {
        __syncthreads();
        #pragma unroll
        for (int j = tid; j < TILE_P; j += TPB) {
            s_xy[j] = gxy[t * TILE_P + j];
            s_zh[j] = gzh[t * TILE_P + j];
        }
        __syncthreads();

        const ulonglong2* __restrict__ axy = (const ulonglong2*)s_xy;
        const ulonglong2* __restrict__ azh = (const ulonglong2*)s_zh;

        #pragma unroll 4
        for (int j = 0; j < TILE_P; j++) {
            const ulonglong2 A = axy[j];   // A.x = (x0,x1), A.y = (y0,y1)
            const ulonglong2 B = azh[j];   // B.x = (z0,z1), B.y = (h0,h1)
            ull v0 = fma2(nz0, B.x, B.y);
            v0 = fma2(ny0, A.y, v0);
            v0 = fma2(nx0, A.x, v0);
            ull v1 = fma2(nz1, B.x, B.y);
            v1 = fma2(ny1, A.y, v1);
            v1 = fma2(nx1, A.x, v1);
            float l0, h0, l1, h1;
            unpack2(v0, l0, h0);
            unpack2(v1, l1, h1);
            m0a = fminf(m0a, l0);
            m0b = fminf(m0b, h0);
            m1a = fminf(m1a, l1);
            m1b = fminf(m1b, h1);
        }
    }

    const float d0 = sqrtf(fmaxf(2.0f * (fminf(m0a, m0b) + q0.w), 0.0f));
    const float d1 = sqrtf(fmaxf(2.0f * (fminf(m1a, m1b) + q1.w), 0.0f));

    float s = block_reduce_sum(d0 + d1);

    __shared__ bool is_last;
    const int blk = (blockIdx.z * BB + blockIdx.y) * NCHUNK + blockIdx.x;
    if (tid == 0) {
        g_partials[blk] = s;
        __threadfence();
        is_last = (atomicAdd(&g_count, 1u) == NBLK - 1);
    }
    __syncthreads();

    if (is_last) {
        const volatile float* vp = g_partials;
        float v = (tid < NBLK) ? vp[tid] : 0.f;
        float tot = block_reduce_sum(v);
        if (tid == 0) {
            out[0] = tot * (1.0f / (BB * NN));
            g_count = 0;                      // reset for next graph replay
        }
    }
}

// ---------------------------------------------------------------------------
extern "C" void kernel_launch(void* const* d_in, const int* in_sizes, int n_in,
                              void* d_out, int out_size)
{
    const float* pred_rot      = (const float*)d_in[0];
    const float* pred_trans    = (const float*)d_in[1];
    const float* ctx_hyp_rot   = (const float*)d_in[2];
    const float* ctx_hyp_trans = (const float*)d_in[3];
    const float* gt_rot        = (const float*)d_in[4];
    const float* gt_trans      = (const float*)d_in[5];
    const float* ctx_gt_rot    = (const float*)d_in[6];
    const float* ctx_gt_trans  = (const float*)d_in[7];
    const float* model_points  = (const float*)d_in[8];
    float* out = (float*)d_out;

    k_prep<<<(BB * NN / 2) / TPB, TPB>>>(pred_rot, pred_trans,
                                         ctx_hyp_rot, ctx_hyp_trans,
                                         gt_rot, gt_trans,
                                         ctx_gt_rot, ctx_gt_trans,
                                         model_points, out);
    k_chamfer<<<dim3(NCHUNK, BB, 2), TPB>>>(out);
}

// round 3
// speedup vs baseline: 1.6170x; 1.1416x over previous
#include <cuda_runtime.h>
#include <math.h>

#define BB   8
#define NN   4096
#define TPB  256
#define QPT  4                     // queries per thread
#define QPB  (TPB * QPT)           // 1024 queries per block
#define NQCH (NN / QPB)            // 4 query chunks
#define NTCH 4                     // target chunks
#define TGT_PER_BLK (NN / NTCH)    // 1024 targets per block
#define TILE_P (TGT_PER_BLK / 2)   // 512 packed target-pairs
#define PSTEPS (NN / 2)            // 2048 packed pairs total
#define NRED_BLK 64                // reduce-kernel blocks
#define QTOT (2 * BB * NN)         // 65536 query-min slots

typedef unsigned long long ull;

// Scratch (__device__ globals; allocation forbidden)
__device__ float4 g_xy[2][BB][PSTEPS];   // (x0,x1,y0,y1) packed target pairs
__device__ float4 g_zh[2][BB][PSTEPS];   // (z0,z1,h0,h1), h = 0.5*|p|^2
__device__ float4 g_q [2][BB][NN];       // AoS queries (x,y,z,h)
__device__ float  g_h [2][BB][NN];       // query half-norms (coalesced for reduce)
__device__ unsigned int g_minenc[QTOT];  // order-encoded per-query mins
__device__ float  g_partials[NRED_BLK];
__device__ unsigned int g_count = 0;

// ---- packed f32x2 helpers (sm_103a) --------------------------------------
__device__ __forceinline__ ull fma2(ull a, ull b, ull c) {
    ull d;
    asm("fma.rn.f32x2 %0, %1, %2, %3;" : "=l"(d) : "l"(a), "l"(b), "l"(c));
    return d;
}
__device__ __forceinline__ ull pack2(float lo, float hi) {
    ull r;
    asm("mov.b64 %0, {%1, %2};" : "=l"(r) : "f"(lo), "f"(hi));
    return r;
}
__device__ __forceinline__ void unpack2(ull v, float& lo, float& hi) {
    asm("mov.b64 {%0, %1}, %2;" : "=f"(lo), "=f"(hi) : "l"(v));
}
// order-preserving float<->uint encode (no NaNs in this workload)
__device__ __forceinline__ unsigned int enc_f(float f) {
    unsigned int u = __float_as_uint(f);
    return ((int)u >= 0) ? (u ^ 0x80000000u) : ~u;
}
__device__ __forceinline__ float dec_f(unsigned int k) {
    return (k & 0x80000000u) ? __uint_as_float(k ^ 0x80000000u)
                             : __uint_as_float(~k);
}

// ---------------------------------------------------------------------------
// Kernel 1: rel transforms (per-block in smem) + loss_trans + point transform
//           into packed SoA + init g_minenc for this replay.
// grid: BB*NN/2 threads (64 blocks), each thread handles 2 consecutive points.
// ---------------------------------------------------------------------------
__global__ void __launch_bounds__(TPB) k_prep(
    const float* __restrict__ pred_rot,   const float* __restrict__ pred_trans,
    const float* __restrict__ ctx_hyp_rot,const float* __restrict__ ctx_hyp_trans,
    const float* __restrict__ gt_rot,     const float* __restrict__ gt_trans,
    const float* __restrict__ ctx_gt_rot, const float* __restrict__ ctx_gt_trans,
    const float* __restrict__ mp,         float* __restrict__ out)
{
    __shared__ float sR[2][BB][9];
    __shared__ float sT[2][BB][3];

    const int tid = threadIdx.x;
    if (tid < 2 * BB) {
        const int w = tid / BB, b = tid % BB;
        const float* Ra = (w == 0 ? pred_rot      : gt_rot)       + b * 9;
        const float* ta = (w == 0 ? pred_trans    : gt_trans)     + b * 3;
        const float* Rb = (w == 0 ? ctx_hyp_rot   : ctx_gt_rot)   + b * 9;
        const float* tb = (w == 0 ? ctx_hyp_trans : ctx_gt_trans) + b * 3;
        #pragma unroll
        for (int i = 0; i < 3; i++)
            #pragma unroll
            for (int k = 0; k < 3; k++) {
                float s = 0.f;
                #pragma unroll
                for (int j = 0; j < 3; j++) s += Ra[i*3+j] * Rb[k*3+j];
                sR[w][b][i*3+k] = s;
            }
        #pragma unroll
        for (int i = 0; i < 3; i++) {
            float s = ta[i];
            #pragma unroll
            for (int j = 0; j < 3; j++) s -= sR[w][b][i*3+j] * tb[j];
            sT[w][b][i] = s;
        }
    }
    __syncthreads();

    if (blockIdx.x == 0 && tid == 0) {
        float s = 0.f;
        for (int b = 0; b < BB; b++)
            for (int i = 0; i < 3; i++)
                s += fabsf(sT[0][b][i] - sT[1][b][i]);
        out[1] = s * (1.0f / (BB * 3));
    }

    const int idx = blockIdx.x * TPB + tid;          // < BB*NN/2 = 16384
    // init 4 min slots per thread (65536 total)
    #pragma unroll
    for (int k = 0; k < 4; k++)
        g_minenc[idx + k * (BB * NN / 2)] = 0xFFFFFFFFu;

    const int b = idx / PSTEPS;
    const int i = idx % PSTEPS;
    const float* p = mp + (b * NN + 2 * i) * 3;
    const float p0x = p[0], p0y = p[1], p0z = p[2];
    const float p1x = p[3], p1y = p[4], p1z = p[5];

    #pragma unroll
    for (int w = 0; w < 2; w++) {
        const float* R = sR[w][b];
        const float* t = sT[w][b];
        float x0 = fmaf(R[0], p0x, fmaf(R[1], p0y, fmaf(R[2], p0z, t[0])));
        float y0 = fmaf(R[3], p0x, fmaf(R[4], p0y, fmaf(R[5], p0z, t[1])));
        float z0 = fmaf(R[6], p0x, fmaf(R[7], p0y, fmaf(R[8], p0z, t[2])));
        float h0 = 0.5f * fmaf(x0, x0, fmaf(y0, y0, z0 * z0));
        float x1 = fmaf(R[0], p1x, fmaf(R[1], p1y, fmaf(R[2], p1z, t[0])));
        float y1 = fmaf(R[3], p1x, fmaf(R[4], p1y, fmaf(R[5], p1z, t[1])));
        float z1 = fmaf(R[6], p1x, fmaf(R[7], p1y, fmaf(R[8], p1z, t[2])));
        float h1 = 0.5f * fmaf(x1, x1, fmaf(y1, y1, z1 * z1));
        g_xy[w][b][i] = make_float4(x0, x1, y0, y1);
        g_zh[w][b][i] = make_float4(z0, z1, h0, h1);
        g_q [w][b][2*i  ] = make_float4(x0, y0, z0, h0);
        g_q [w][b][2*i+1] = make_float4(x1, y1, z1, h1);
        g_h [w][b][2*i  ] = h0;
        g_h [w][b][2*i+1] = h1;
    }
}

// ---------------------------------------------------------------------------
// Deterministic block sum reduction (valid in thread 0)
// ---------------------------------------------------------------------------
__device__ __forceinline__ float block_reduce_sum(float v)
{
    __shared__ float ws[TPB / 32];
    #pragma unroll
    for (int o = 16; o > 0; o >>= 1) v += __shfl_down_sync(0xffffffffu, v, o);
    if ((threadIdx.x & 31) == 0) ws[threadIdx.x >> 5] = v;
    __syncthreads();
    if (threadIdx.x < 32) {
        v = (threadIdx.x < TPB / 32) ? ws[threadIdx.x] : 0.f;
        #pragma unroll
        for (int o = 4; o > 0; o >>= 1) v += __shfl_down_sync(0xffffffffu, v, o);
    }
    return v;
}

// ---------------------------------------------------------------------------
// Kernel 2: chamfer partial mins. grid (NQCH, BB, 2*NTCH), 256 thr, QPT=4.
// Each block: 1024 queries x 1024 targets; single 16KB smem tile, no sync in
// the hot loop. min over targets of (h_t - q.t), combined across target
// chunks via exact atomicMin on order-encoded uints (deterministic).
// ---------------------------------------------------------------------------
__global__ void __launch_bounds__(TPB) k_chamfer()
{
    __shared__ float4 s_xy[TILE_P];
    __shared__ float4 s_zh[TILE_P];

    const int dir = blockIdx.z >> 2;
    const int tq  = blockIdx.z & 3;
    const int b   = blockIdx.y;
    const int tid = threadIdx.x;

    // load target tile (1024 targets = 512 packed pairs)
    {
        const float4* __restrict__ gxy = &g_xy[1 - dir][b][tq * TILE_P];
        const float4* __restrict__ gzh = &g_zh[1 - dir][b][tq * TILE_P];
        #pragma unroll
        for (int j = tid; j < TILE_P; j += TPB) {
            s_xy[j] = gxy[j];
            s_zh[j] = gzh[j];
        }
    }

    // load 4 queries
    const int nbase = blockIdx.x * QPB + tid;
    ull nx[QPT], ny[QPT], nz[QPT];
    #pragma unroll
    for (int k = 0; k < QPT; k++) {
        float4 q = g_q[dir][b][nbase + k * TPB];
        nx[k] = pack2(-q.x, -q.x);
        ny[k] = pack2(-q.y, -q.y);
        nz[k] = pack2(-q.z, -q.z);
    }

    float ma[QPT], mb[QPT];
    #pragma unroll
    for (int k = 0; k < QPT; k++) { ma[k] = INFINITY; mb[k] = INFINITY; }

    __syncthreads();

    const ulonglong2* __restrict__ axy = (const ulonglong2*)s_xy;
    const ulonglong2* __restrict__ azh = (const ulonglong2*)s_zh;

    #pragma unroll 4
    for (int j = 0; j < TILE_P; j++) {
        const ulonglong2 A = axy[j];   // (x0,x1) (y0,y1)
        const ulonglong2 B = azh[j];   // (z0,z1) (h0,h1)
        #pragma unroll
        for (int k = 0; k < QPT; k++) {
            ull v = fma2(nz[k], B.x, B.y);
            v = fma2(ny[k], A.y, v);
            v = fma2(nx[k], A.x, v);
            float lo, hi;
            unpack2(v, lo, hi);
            ma[k] = fminf(ma[k], lo);
            mb[k] = fminf(mb[k], hi);
        }
    }

    #pragma unroll
    for (int k = 0; k < QPT; k++) {
        const unsigned int key = enc_f(fminf(ma[k], mb[k]));
        atomicMin(&g_minenc[(dir * BB + b) * NN + nbase + k * TPB], key);
    }
}

// ---------------------------------------------------------------------------
// Kernel 3: decode mins, deferred sqrt, global sum -> loss_geo.
// grid NRED_BLK x 256, 4 values/thread; counter-based last-block final.
// ---------------------------------------------------------------------------
__global__ void __launch_bounds__(TPB) k_reduce(float* __restrict__ out)
{
    const int tid  = threadIdx.x;
    const int base = blockIdx.x * (QTOT / NRED_BLK) + tid;   // 1024 per block
    const float* __restrict__ hflat = &g_h[0][0][0];

    float s = 0.f;
    #pragma unroll
    for (int k = 0; k < 4; k++) {
        const int q = base + k * TPB;
        const float m = dec_f(g_minenc[q]);
        const float h = hflat[q];
        s += sqrtf(fmaxf(2.0f * (m + h), 0.0f));
    }

    float bs = block_reduce_sum(s);

    __shared__ bool is_last;
    if (tid == 0) {
        g_partials[blockIdx.x] = bs;
        __threadfence();
        is_last = (atomicAdd(&g_count, 1u) == NRED_BLK - 1);
    }
    __syncthreads();

    if (is_last) {
        const volatile float* vp = g_partials;
        float v = (tid < NRED_BLK) ? vp[tid] : 0.f;
        float tot = block_reduce_sum(v);
        if (tid == 0) {
            out[0] = tot * (1.0f / (BB * NN));
            g_count = 0;   // reset for next graph replay
        }
    }
}

// ---------------------------------------------------------------------------
extern "C" void kernel_launch(void* const* d_in, const int* in_sizes, int n_in,
                              void* d_out, int out_size)
{
    const float* pred_rot      = (const float*)d_in[0];
    const float* pred_trans    = (const float*)d_in[1];
    const float* ctx_hyp_rot   = (const float*)d_in[2];
    const float* ctx_hyp_trans = (const float*)d_in[3];
    const float* gt_rot        = (const float*)d_in[4];
    const float* gt_trans      = (const float*)d_in[5];
    const float* ctx_gt_rot    = (const float*)d_in[6];
    const float* ctx_gt_trans  = (const float*)d_in[7];
    const float* model_points  = (const float*)d_in[8];
    float* out = (float*)d_out;

    k_prep<<<(BB * NN / 2) / TPB, TPB>>>(pred_rot, pred_trans,
                                         ctx_hyp_rot, ctx_hyp_trans,
                                         gt_rot, gt_trans,
                                         ctx_gt_rot, ctx_gt_trans,
                                         model_points, out);
    k_chamfer<<<dim3(NQCH, BB, 2 * NTCH), TPB>>>();
    k_reduce<<<NRED_BLK, TPB>>>(out);
}